// round 1
// baseline (speedup 1.0000x reference)
#include <cuda_runtime.h>

#define B_ 16
#define S_ 2048
#define D_ 1024
#define H_ 128
#define M_TOT (B_*S_)

// Scratch for Q/K/V projections (allocation-free rule -> __device__ globals)
__device__ float g_q[M_TOT * H_];
__device__ float g_k[M_TOT * H_];
__device__ float g_v[M_TOT * H_];

// ---------------------------------------------------------------------------
// Kernel 1: fused QKV projection.  C[32768,128] = A[32768,1024] * W[1024,128]
// blockIdx.z selects Wq/Wk/Wv.  BM=128, BN=128(all of H), BK=8, 256 threads,
// 8x8 register microtile per thread.
// ---------------------------------------------------------------------------
__global__ __launch_bounds__(256) void qkv_gemm_kernel(
    const float* __restrict__ A,
    const float* __restrict__ Wq,
    const float* __restrict__ Wk,
    const float* __restrict__ Wv)
{
    __shared__ float As[8][132];   // A tile transposed: As[kk][m], stride 132 keeps 16B align
    __shared__ float Bs[8][128];   // W tile: Bs[kk][n]

    const float* W;
    float* C;
    if (blockIdx.z == 0)      { W = Wq; C = g_q; }
    else if (blockIdx.z == 1) { W = Wk; C = g_k; }
    else                      { W = Wv; C = g_v; }

    const int tid = threadIdx.x;
    const int ty  = tid >> 4;        // 0..15 (row group)
    const int tx  = tid & 15;        // 0..15 (col group)
    const int m0  = blockIdx.x * 128;

    const int arow  = tid >> 1;      // 0..127
    const int apart = tid & 1;       // which float4 of the 8-wide A row slab
    const int brow  = tid >> 5;      // 0..7
    const int bcol  = (tid & 31) << 2;

    float acc[8][8];
    #pragma unroll
    for (int i = 0; i < 8; i++)
        #pragma unroll
        for (int j = 0; j < 8; j++) acc[i][j] = 0.f;

    for (int k0 = 0; k0 < D_; k0 += 8) {
        float4 av = *(const float4*)(A + (size_t)(m0 + arow) * D_ + k0 + apart * 4);
        float4 bv = *(const float4*)(W + (size_t)(k0 + brow) * H_ + bcol);
        __syncthreads();
        As[apart * 4 + 0][arow] = av.x;
        As[apart * 4 + 1][arow] = av.y;
        As[apart * 4 + 2][arow] = av.z;
        As[apart * 4 + 3][arow] = av.w;
        *(float4*)&Bs[brow][bcol] = bv;
        __syncthreads();

        #pragma unroll
        for (int kk = 0; kk < 8; kk++) {
            float4 a0 = *(const float4*)&As[kk][ty * 8];
            float4 a1 = *(const float4*)&As[kk][ty * 8 + 4];
            float4 b0 = *(const float4*)&Bs[kk][tx * 8];
            float4 b1 = *(const float4*)&Bs[kk][tx * 8 + 4];
            float a[8] = {a0.x, a0.y, a0.z, a0.w, a1.x, a1.y, a1.z, a1.w};
            float b[8] = {b0.x, b0.y, b0.z, b0.w, b1.x, b1.y, b1.z, b1.w};
            #pragma unroll
            for (int i = 0; i < 8; i++)
                #pragma unroll
                for (int j = 0; j < 8; j++)
                    acc[i][j] = fmaf(a[i], b[j], acc[i][j]);
        }
    }

    #pragma unroll
    for (int i = 0; i < 8; i++) {
        float4 c0 = make_float4(acc[i][0], acc[i][1], acc[i][2], acc[i][3]);
        float4 c1 = make_float4(acc[i][4], acc[i][5], acc[i][6], acc[i][7]);
        float* dst = C + (size_t)(m0 + ty * 8 + i) * H_ + tx * 8;
        *(float4*)dst       = c0;
        *(float4*)(dst + 4) = c1;
    }
}

// ---------------------------------------------------------------------------
// Kernel 2: causal flash attention, fp32.
// One CTA = 64 query rows of one batch. 256 threads (16x16 grid).
// S-GEMM: 4x4 microtile.  O-GEMM: 4x8 microtile (P staged via smem).
// ---------------------------------------------------------------------------
#define BM 64
#define BN 64
#define QKS 68                                   // padded stride for transposed tiles
#define SMEM_FLOATS (2 * 128 * QKS + 64 * 128 + 64 * QKS)
#define SMEM_BYTES  (SMEM_FLOATS * 4)

__global__ __launch_bounds__(256) void attn_kernel(float* __restrict__ out)
{
    extern __shared__ float smem[];
    float* Qt = smem;                    // [128][QKS]  Qt[h][m], pre-scaled
    float* Kt = Qt + 128 * QKS;          // [128][QKS]  Kt[h][n]
    float* Vs = Kt + 128 * QKS;          // [64][128]   Vs[t][h]
    float* Pt = Vs + 64 * 128;           // [64][QKS]   Pt[t][m]

    const int tid = threadIdx.x;
    const int ty  = tid >> 4;            // 0..15
    const int tx  = tid & 15;            // 0..15
    const int b   = blockIdx.y;
    const int it  = blockIdx.x;          // query tile index
    const int q0  = it * BM;

    const float* gq = g_q + (size_t)b * S_ * H_;
    const float* gk = g_k + (size_t)b * S_ * H_;
    const float* gv = g_v + (size_t)b * S_ * H_;

    const float scale = 0.0883883476483184405f;  // 1/sqrt(128)

    // Load Q tile transposed + pre-scaled
    #pragma unroll
    for (int i = 0; i < 8; i++) {
        int u   = tid + i * 256;         // 0..2047 float4 slots
        int row = u >> 5;                // 0..63
        int c4  = (u & 31) << 2;         // 0..124
        float4 v = *(const float4*)(gq + (size_t)(q0 + row) * H_ + c4);
        Qt[(c4 + 0) * QKS + row] = v.x * scale;
        Qt[(c4 + 1) * QKS + row] = v.y * scale;
        Qt[(c4 + 2) * QKS + row] = v.z * scale;
        Qt[(c4 + 3) * QKS + row] = v.w * scale;
    }

    float o[4][8];
    #pragma unroll
    for (int i = 0; i < 4; i++)
        #pragma unroll
        for (int j = 0; j < 8; j++) o[i][j] = 0.f;
    float mrow[4] = {-INFINITY, -INFINITY, -INFINITY, -INFINITY};
    float lrow[4] = {0.f, 0.f, 0.f, 0.f};

    for (int j = 0; j <= it; j++) {
        const int t0 = j * BN;
        __syncthreads();   // protect Kt/Vs/Pt from previous iteration readers

        // Load K tile (transposed) and V tile (direct)
        #pragma unroll
        for (int i = 0; i < 8; i++) {
            int u   = tid + i * 256;
            int row = u >> 5;
            int c4  = (u & 31) << 2;
            float4 kv = *(const float4*)(gk + (size_t)(t0 + row) * H_ + c4);
            Kt[(c4 + 0) * QKS + row] = kv.x;
            Kt[(c4 + 1) * QKS + row] = kv.y;
            Kt[(c4 + 2) * QKS + row] = kv.z;
            Kt[(c4 + 3) * QKS + row] = kv.w;
            float4 vv = *(const float4*)(gv + (size_t)(t0 + row) * H_ + c4);
            *(float4*)&Vs[row * H_ + c4] = vv;
        }
        __syncthreads();

        // S = (Q*scale) K^T  -- 4x4 fragment per thread
        float s[4][4];
        #pragma unroll
        for (int i = 0; i < 4; i++)
            #pragma unroll
            for (int c = 0; c < 4; c++) s[i][c] = 0.f;

        #pragma unroll 8
        for (int kk = 0; kk < 128; kk++) {
            float4 qa = *(const float4*)&Qt[kk * QKS + ty * 4];
            float4 kb = *(const float4*)&Kt[kk * QKS + tx * 4];
            float a[4] = {qa.x, qa.y, qa.z, qa.w};
            float c2[4] = {kb.x, kb.y, kb.z, kb.w};
            #pragma unroll
            for (int i = 0; i < 4; i++)
                #pragma unroll
                for (int c = 0; c < 4; c++)
                    s[i][c] = fmaf(a[i], c2[c], s[i][c]);
        }

        // Causal mask on diagonal tile
        if (j == it) {
            #pragma unroll
            for (int i = 0; i < 4; i++)
                #pragma unroll
                for (int c = 0; c < 4; c++)
                    if (tx * 4 + c > ty * 4 + i) s[i][c] = -INFINITY;
        }

        // Online softmax update
        #pragma unroll
        for (int i = 0; i < 4; i++) {
            float mloc = fmaxf(fmaxf(s[i][0], s[i][1]), fmaxf(s[i][2], s[i][3]));
            #pragma unroll
            for (int ofs = 8; ofs >= 1; ofs >>= 1)
                mloc = fmaxf(mloc, __shfl_xor_sync(0xffffffffu, mloc, ofs));
            float mnew  = fmaxf(mrow[i], mloc);
            float alpha = __expf(mrow[i] - mnew);
            mrow[i] = mnew;

            float p[4], rs = 0.f;
            #pragma unroll
            for (int c = 0; c < 4; c++) {
                p[c] = __expf(s[i][c] - mnew);
                rs += p[c];
            }
            #pragma unroll
            for (int ofs = 8; ofs >= 1; ofs >>= 1)
                rs += __shfl_xor_sync(0xffffffffu, rs, ofs);
            lrow[i] = lrow[i] * alpha + rs;

            #pragma unroll
            for (int c = 0; c < 4; c++)
                Pt[(tx * 4 + c) * QKS + ty * 4 + i] = p[c];
            #pragma unroll
            for (int h = 0; h < 8; h++) o[i][h] *= alpha;
        }
        __syncthreads();   // Pt visible before O-GEMM

        // O += P V  -- 4x8 fragment per thread
        #pragma unroll 4
        for (int t = 0; t < 64; t++) {
            float4 pv = *(const float4*)&Pt[t * QKS + ty * 4];
            float4 v0 = *(const float4*)&Vs[t * H_ + tx * 8];
            float4 v1 = *(const float4*)&Vs[t * H_ + tx * 8 + 4];
            float pr[4] = {pv.x, pv.y, pv.z, pv.w};
            #pragma unroll
            for (int i = 0; i < 4; i++) {
                o[i][0] = fmaf(pr[i], v0.x, o[i][0]);
                o[i][1] = fmaf(pr[i], v0.y, o[i][1]);
                o[i][2] = fmaf(pr[i], v0.z, o[i][2]);
                o[i][3] = fmaf(pr[i], v0.w, o[i][3]);
                o[i][4] = fmaf(pr[i], v1.x, o[i][4]);
                o[i][5] = fmaf(pr[i], v1.y, o[i][5]);
                o[i][6] = fmaf(pr[i], v1.z, o[i][6]);
                o[i][7] = fmaf(pr[i], v1.w, o[i][7]);
            }
        }
    }

    // Normalize and write
    #pragma unroll
    for (int i = 0; i < 4; i++) {
        float rl = 1.f / lrow[i];
        float4 c0 = make_float4(o[i][0] * rl, o[i][1] * rl, o[i][2] * rl, o[i][3] * rl);
        float4 c1 = make_float4(o[i][4] * rl, o[i][5] * rl, o[i][6] * rl, o[i][7] * rl);
        float* dst = out + ((size_t)b * S_ + q0 + ty * 4 + i) * H_ + tx * 8;
        *(float4*)dst       = c0;
        *(float4*)(dst + 4) = c1;
    }
}

// ---------------------------------------------------------------------------
extern "C" void kernel_launch(void* const* d_in, const int* in_sizes, int n_in,
                              void* d_out, int out_size)
{
    const float* input = (const float*)d_in[0];
    const float* Wq    = (const float*)d_in[1];
    const float* Wk    = (const float*)d_in[2];
    const float* Wv    = (const float*)d_in[3];
    float* out = (float*)d_out;

    // Idempotent, capture-safe (not a stream op)
    cudaFuncSetAttribute(attn_kernel, cudaFuncAttributeMaxDynamicSharedMemorySize,
                         SMEM_BYTES);

    dim3 g1(M_TOT / 128, 1, 3);
    qkv_gemm_kernel<<<g1, 256>>>(input, Wq, Wk, Wv);

    dim3 g2(S_ / BM, B_);
    attn_kernel<<<g2, 256, SMEM_BYTES>>>(out);
}

// round 3
// speedup vs baseline: 3.1346x; 3.1346x over previous
#include <cuda_runtime.h>
#include <cuda_bf16.h>
#include <cstdint>

#define B_ 16
#define S_ 2048
#define D_ 1024
#define H_ 128
#define M_TOT (B_*S_)

// ---------------- scratch (__device__ globals; allocation-free rule) -------
__device__ __nv_bfloat16 g_a_hi[(size_t)M_TOT * D_];
__device__ __nv_bfloat16 g_a_lo[(size_t)M_TOT * D_];
__device__ __nv_bfloat16 g_wt_hi[3 * H_ * D_];   // [z][n][k] (W transposed)
__device__ __nv_bfloat16 g_wt_lo[3 * H_ * D_];
__device__ __nv_bfloat16 g_qh[M_TOT * H_], g_ql[M_TOT * H_];
__device__ __nv_bfloat16 g_kh[M_TOT * H_], g_kl[M_TOT * H_];
__device__ __nv_bfloat16 g_vh[M_TOT * H_], g_vl[M_TOT * H_];

// ---------------- helpers (all sm_80-baseline, family-target safe) ---------
__device__ __forceinline__ uint32_t smem_u32(const void* p) {
    uint32_t a;
    asm("{ .reg .u64 t; cvta.to.shared.u64 t, %1; cvt.u32.u64 %0, t; }"
        : "=r"(a) : "l"(p));
    return a;
}
__device__ __forceinline__ void cp16(uint32_t dst, const void* src) {
    asm volatile("cp.async.cg.shared.global [%0], [%1], 16;" :: "r"(dst), "l"(src));
}
#define CP_COMMIT() asm volatile("cp.async.commit_group;" ::: "memory")
#define CP_WAIT0()  asm volatile("cp.async.wait_group 0;" ::: "memory")

__device__ __forceinline__ void ldsm_x4(uint32_t r[4], uint32_t addr) {
    asm volatile("ldmatrix.sync.aligned.m8n8.x4.shared.b16 {%0,%1,%2,%3}, [%4];"
        : "=r"(r[0]), "=r"(r[1]), "=r"(r[2]), "=r"(r[3]) : "r"(addr));
}
__device__ __forceinline__ void ldsm_x4_t(uint32_t r[4], uint32_t addr) {
    asm volatile("ldmatrix.sync.aligned.m8n8.x4.trans.shared.b16 {%0,%1,%2,%3}, [%4];"
        : "=r"(r[0]), "=r"(r[1]), "=r"(r[2]), "=r"(r[3]) : "r"(addr));
}
__device__ __forceinline__ void mma16816(float c[4], const uint32_t a[4],
                                         const uint32_t b[2]) {
    asm volatile("mma.sync.aligned.m16n8k16.row.col.f32.bf16.bf16.f32 "
        "{%0,%1,%2,%3}, {%4,%5,%6,%7}, {%8,%9}, {%0,%1,%2,%3};"
        : "+f"(c[0]), "+f"(c[1]), "+f"(c[2]), "+f"(c[3])
        : "r"(a[0]), "r"(a[1]), "r"(a[2]), "r"(a[3]), "r"(b[0]), "r"(b[1]));
}
// split two floats into packed bf16 hi and lo (x = hi + lo)
__device__ __forceinline__ void split2(float x0, float x1, uint32_t& h, uint32_t& l) {
    __nv_bfloat16 h0 = __float2bfloat16(x0), h1 = __float2bfloat16(x1);
    __nv_bfloat162 hp = __halves2bfloat162(h0, h1);
    h = *(uint32_t*)&hp;
    __nv_bfloat16 l0 = __float2bfloat16(x0 - __bfloat162float(h0));
    __nv_bfloat16 l1 = __float2bfloat16(x1 - __bfloat162float(h1));
    __nv_bfloat162 lp = __halves2bfloat162(l0, l1);
    l = *(uint32_t*)&lp;
}

// ---------------------------------------------------------------------------
// Kernel 0a: fp32 input -> bf16 hi/lo split
// ---------------------------------------------------------------------------
__global__ __launch_bounds__(256) void convert_a_kernel(const float* __restrict__ in)
{
    int i = blockIdx.x * 256 + threadIdx.x;         // float4 index
    float4 v = ((const float4*)in)[i];
    __nv_bfloat16 h0 = __float2bfloat16(v.x), h1 = __float2bfloat16(v.y);
    __nv_bfloat16 h2 = __float2bfloat16(v.z), h3 = __float2bfloat16(v.w);
    __nv_bfloat16 l0 = __float2bfloat16(v.x - __bfloat162float(h0));
    __nv_bfloat16 l1 = __float2bfloat16(v.y - __bfloat162float(h1));
    __nv_bfloat16 l2 = __float2bfloat16(v.z - __bfloat162float(h2));
    __nv_bfloat16 l3 = __float2bfloat16(v.w - __bfloat162float(h3));
    uint2 hp, lp;
    hp.x = (uint32_t)__bfloat16_as_ushort(h0) | ((uint32_t)__bfloat16_as_ushort(h1) << 16);
    hp.y = (uint32_t)__bfloat16_as_ushort(h2) | ((uint32_t)__bfloat16_as_ushort(h3) << 16);
    lp.x = (uint32_t)__bfloat16_as_ushort(l0) | ((uint32_t)__bfloat16_as_ushort(l1) << 16);
    lp.y = (uint32_t)__bfloat16_as_ushort(l2) | ((uint32_t)__bfloat16_as_ushort(l3) << 16);
    ((uint2*)g_a_hi)[i] = hp;
    ((uint2*)g_a_lo)[i] = lp;
}

// ---------------------------------------------------------------------------
// Kernel 0b: W [1024,128] fp32 -> transposed bf16 hi/lo [128,1024]
// ---------------------------------------------------------------------------
__global__ __launch_bounds__(256) void convert_w_kernel(
    const float* __restrict__ Wq, const float* __restrict__ Wk,
    const float* __restrict__ Wv)
{
    int z = blockIdx.y;
    const float* W = (z == 0) ? Wq : (z == 1) ? Wk : Wv;
    int idx = blockIdx.x * 256 + threadIdx.x;
    int k = idx >> 7, n = idx & 127;
    float x = W[idx];
    __nv_bfloat16 h = __float2bfloat16(x);
    __nv_bfloat16 l = __float2bfloat16(x - __bfloat162float(h));
    size_t o = (size_t)(z * H_ + n) * D_ + k;
    g_wt_hi[o] = h;
    g_wt_lo[o] = l;
}

// ---------------------------------------------------------------------------
// Kernel 1: QKV projection via mma.sync bf16 3-term split.
// CTA: 128 rows x 128 cols, 8 warps (warp tile 32x64), grid.z = q/k/v.
// K chunks of 64 via cp.async, 2 CTAs/SM.
// ---------------------------------------------------------------------------
#define A_HI 0
#define A_LO (128*144)
#define W_HI (2*128*144)
#define W_LO (3*128*144)
#define QKV_SMEM (4*128*144)     // 73728 bytes; rows padded to 144B (9x16B)

__global__ __launch_bounds__(256, 2) void qkv_gemm()
{
    extern __shared__ char smc[];
    const uint32_t sb = smem_u32(smc);
    const int tid = threadIdx.x, lane = tid & 31, wid = tid >> 5;
    const int wm = wid >> 1, wn = wid & 1;
    const int m0 = blockIdx.x * 128, z = blockIdx.z;
    const int g = lane >> 2, tg = lane & 3;

    const __nv_bfloat16* wt_h = g_wt_hi + (size_t)z * H_ * D_;
    const __nv_bfloat16* wt_l = g_wt_lo + (size_t)z * H_ * D_;

    float acc[2][8][4];
    #pragma unroll
    for (int a = 0; a < 2; a++)
        #pragma unroll
        for (int b = 0; b < 8; b++)
            #pragma unroll
            for (int c = 0; c < 4; c++) acc[a][b][c] = 0.f;

    for (int ch = 0; ch < 16; ch++) {
        const int k0 = ch * 64;
        #pragma unroll
        for (int i = 0; i < 4; i++) {
            int u = tid + i * 256, row = u >> 3, c = u & 7;
            uint32_t d = (uint32_t)(row * 144 + c * 16);
            size_t ga = (size_t)(m0 + row) * D_ + k0 + c * 8;
            size_t gw = (size_t)row * D_ + k0 + c * 8;
            cp16(sb + A_HI + d, g_a_hi + ga);
            cp16(sb + A_LO + d, g_a_lo + ga);
            cp16(sb + W_HI + d, wt_h + gw);
            cp16(sb + W_LO + d, wt_l + gw);
        }
        CP_COMMIT(); CP_WAIT0();
        __syncthreads();

        #pragma unroll
        for (int s = 0; s < 4; s++) {
            uint32_t ah[2][4], al[2][4];
            #pragma unroll
            for (int mt = 0; mt < 2; mt++) {
                uint32_t ar = (uint32_t)((wm * 32 + mt * 16 + (lane & 15)) * 144
                               + (s * 16 + (lane >> 4) * 8) * 2);
                ldsm_x4(ah[mt], sb + A_HI + ar);
                ldsm_x4(al[mt], sb + A_LO + ar);
            }
            #pragma unroll
            for (int p = 0; p < 4; p++) {
                uint32_t br = (uint32_t)((wn * 64 + p * 16 + (lane >> 4) * 8 + (lane & 7)) * 144
                               + (s * 16 + ((lane >> 3) & 1) * 8) * 2);
                uint32_t bh[4], bl[4];
                ldsm_x4(bh, sb + W_HI + br);
                ldsm_x4(bl, sb + W_LO + br);
                #pragma unroll
                for (int mt = 0; mt < 2; mt++) {
                    mma16816(acc[mt][2*p],   ah[mt], bh);
                    mma16816(acc[mt][2*p],   ah[mt], bl);
                    mma16816(acc[mt][2*p],   al[mt], bh);
                    mma16816(acc[mt][2*p+1], ah[mt], bh + 2);
                    mma16816(acc[mt][2*p+1], ah[mt], bl + 2);
                    mma16816(acc[mt][2*p+1], al[mt], bh + 2);
                }
            }
        }
        __syncthreads();
    }

    __nv_bfloat16 *oh, *ol;
    if (z == 0)      { oh = g_qh; ol = g_ql; }
    else if (z == 1) { oh = g_kh; ol = g_kl; }
    else             { oh = g_vh; ol = g_vl; }
    const float scl = (z == 0) ? 0.0883883476483184405f : 1.0f;  // fold 1/sqrt(H) into Q

    #pragma unroll
    for (int mt = 0; mt < 2; mt++)
        #pragma unroll
        for (int nt = 0; nt < 8; nt++) {
            float c0 = acc[mt][nt][0] * scl, c1 = acc[mt][nt][1] * scl;
            float c2 = acc[mt][nt][2] * scl, c3 = acc[mt][nt][3] * scl;
            int r0  = m0 + wm * 32 + mt * 16 + g;
            int col = wn * 64 + nt * 8 + tg * 2;
            uint32_t h01, l01, h23, l23;
            split2(c0, c1, h01, l01);
            split2(c2, c3, h23, l23);
            *(uint32_t*)(oh + (size_t)r0 * H_ + col)       = h01;
            *(uint32_t*)(ol + (size_t)r0 * H_ + col)       = l01;
            *(uint32_t*)(oh + (size_t)(r0 + 8) * H_ + col) = h23;
            *(uint32_t*)(ol + (size_t)(r0 + 8) * H_ + col) = l23;
        }
}

// ---------------------------------------------------------------------------
// Kernel 2: causal flash attention via mma.sync bf16 3-term split.
// CTA = 64 queries, 4 warps (warp = 16 query rows). Key tiles of 64.
// K/V consumed in natural [t][h] layout (K: plain ldmatrix as col-major B,
// V: ldmatrix.trans). S fragments remapped in-register to P A-fragments.
// 2 CTAs/SM; heavy query tiles launched first.
// ---------------------------------------------------------------------------
#define K_HI 0
#define K_LO (64*272)
#define V_HI (2*64*272)
#define V_LO (3*64*272)
#define ATT_SMEM (4*64*272)      // 69632 bytes; rows padded to 272B (17x16B)

__global__ __launch_bounds__(128, 2) void attn_mma(float* __restrict__ out)
{
    extern __shared__ char smc[];
    const uint32_t sb = smem_u32(smc);
    const int tid = threadIdx.x, lane = tid & 31, w = tid >> 5;
    const int b  = blockIdx.y;
    const int it = 31 - blockIdx.x;          // heavy tiles first
    const int q0 = it * 64;
    const int g = lane >> 2, tg = lane & 3;
    const size_t base = (size_t)b * S_ * H_;

    // ---- stage Q, capture fragments in registers ----
    uint32_t qh[8][4], ql[8][4];
    #pragma unroll
    for (int i = 0; i < 8; i++) {
        int u = tid + i * 128, row = u >> 4, c = u & 15;
        uint32_t d = (uint32_t)(row * 272 + c * 16);
        size_t go = base + (size_t)(q0 + row) * H_ + c * 8;
        cp16(sb + K_HI + d, g_qh + go);
        cp16(sb + K_LO + d, g_ql + go);
    }
    CP_COMMIT(); CP_WAIT0();
    __syncthreads();
    #pragma unroll
    for (int s = 0; s < 8; s++) {
        uint32_t ar = (uint32_t)((w * 16 + (lane & 15)) * 272
                       + (s * 16 + (lane >> 4) * 8) * 2);
        ldsm_x4(qh[s], sb + K_HI + ar);
        ldsm_x4(ql[s], sb + K_LO + ar);
    }
    __syncthreads();   // done reading Q staging before K/V loads overwrite

    float o[16][4];
    #pragma unroll
    for (int f = 0; f < 16; f++)
        #pragma unroll
        for (int c = 0; c < 4; c++) o[f][c] = 0.f;
    float m0r = -INFINITY, m1r = -INFINITY, l0 = 0.f, l1 = 0.f;

    for (int j = 0; j <= it; j++) {
        const int t0 = j * 64;
        #pragma unroll
        for (int i = 0; i < 8; i++) {
            int u = tid + i * 128, row = u >> 4, c = u & 15;
            uint32_t d = (uint32_t)(row * 272 + c * 16);
            size_t go = base + (size_t)(t0 + row) * H_ + c * 8;
            cp16(sb + K_HI + d, g_kh + go);
            cp16(sb + K_LO + d, g_kl + go);
            cp16(sb + V_HI + d, g_vh + go);
            cp16(sb + V_LO + d, g_vl + go);
        }
        CP_COMMIT(); CP_WAIT0();
        __syncthreads();

        // ---- S = Q K^T ----
        float s[8][4];
        #pragma unroll
        for (int nt = 0; nt < 8; nt++)
            #pragma unroll
            for (int c = 0; c < 4; c++) s[nt][c] = 0.f;

        #pragma unroll
        for (int ks = 0; ks < 8; ks++) {
            #pragma unroll
            for (int p = 0; p < 4; p++) {
                uint32_t br = (uint32_t)((p * 16 + (lane >> 4) * 8 + (lane & 7)) * 272
                               + (ks * 16 + ((lane >> 3) & 1) * 8) * 2);
                uint32_t bh[4], bl[4];
                ldsm_x4(bh, sb + K_HI + br);
                ldsm_x4(bl, sb + K_LO + br);
                mma16816(s[2*p],   qh[ks], bh);
                mma16816(s[2*p],   qh[ks], bl);
                mma16816(s[2*p],   ql[ks], bh);
                mma16816(s[2*p+1], qh[ks], bh + 2);
                mma16816(s[2*p+1], qh[ks], bl + 2);
                mma16816(s[2*p+1], ql[ks], bh + 2);
            }
        }

        // ---- causal mask (diagonal tile only) ----
        if (j == it) {
            int r0 = q0 + w * 16 + g, r1 = r0 + 8;
            #pragma unroll
            for (int nt = 0; nt < 8; nt++) {
                int kc = t0 + nt * 8 + tg * 2;
                if (kc     > r0) s[nt][0] = -INFINITY;
                if (kc + 1 > r0) s[nt][1] = -INFINITY;
                if (kc     > r1) s[nt][2] = -INFINITY;
                if (kc + 1 > r1) s[nt][3] = -INFINITY;
            }
        }

        // ---- online softmax (rows g and g+8; reduce across lane group of 4) --
        float ml0 = -INFINITY, ml1 = -INFINITY;
        #pragma unroll
        for (int nt = 0; nt < 8; nt++) {
            ml0 = fmaxf(ml0, fmaxf(s[nt][0], s[nt][1]));
            ml1 = fmaxf(ml1, fmaxf(s[nt][2], s[nt][3]));
        }
        #pragma unroll
        for (int ofs = 1; ofs <= 2; ofs <<= 1) {
            ml0 = fmaxf(ml0, __shfl_xor_sync(0xffffffffu, ml0, ofs));
            ml1 = fmaxf(ml1, __shfl_xor_sync(0xffffffffu, ml1, ofs));
        }
        float mn0 = fmaxf(m0r, ml0), mn1 = fmaxf(m1r, ml1);
        float a0 = __expf(m0r - mn0), a1 = __expf(m1r - mn1);
        m0r = mn0; m1r = mn1;

        float rs0 = 0.f, rs1 = 0.f;
        #pragma unroll
        for (int nt = 0; nt < 8; nt++) {
            s[nt][0] = __expf(s[nt][0] - mn0); rs0 += s[nt][0];
            s[nt][1] = __expf(s[nt][1] - mn0); rs0 += s[nt][1];
            s[nt][2] = __expf(s[nt][2] - mn1); rs1 += s[nt][2];
            s[nt][3] = __expf(s[nt][3] - mn1); rs1 += s[nt][3];
        }
        #pragma unroll
        for (int ofs = 1; ofs <= 2; ofs <<= 1) {
            rs0 += __shfl_xor_sync(0xffffffffu, rs0, ofs);
            rs1 += __shfl_xor_sync(0xffffffffu, rs1, ofs);
        }
        l0 = l0 * a0 + rs0;
        l1 = l1 * a1 + rs1;
        #pragma unroll
        for (int f = 0; f < 16; f++) {
            o[f][0] *= a0; o[f][1] *= a0;
            o[f][2] *= a1; o[f][3] *= a1;
        }

        // ---- pack P into A-fragments (register remap of S fragments) ----
        uint32_t ph[4][4], pl[4][4];
        #pragma unroll
        for (int s4 = 0; s4 < 4; s4++) {
            split2(s[2*s4][0],   s[2*s4][1],   ph[s4][0], pl[s4][0]);
            split2(s[2*s4][2],   s[2*s4][3],   ph[s4][1], pl[s4][1]);
            split2(s[2*s4+1][0], s[2*s4+1][1], ph[s4][2], pl[s4][2]);
            split2(s[2*s4+1][2], s[2*s4+1][3], ph[s4][3], pl[s4][3]);
        }

        // ---- O += P V  (V via ldmatrix.trans from natural [t][h]) ----
        #pragma unroll
        for (int s4 = 0; s4 < 4; s4++) {
            #pragma unroll
            for (int p = 0; p < 8; p++) {
                uint32_t vr = (uint32_t)((s4 * 16 + (lane & 7) + ((lane >> 3) & 1) * 8) * 272
                               + (p * 2 + (lane >> 4)) * 16);
                uint32_t vh[4], vl[4];
                ldsm_x4_t(vh, sb + V_HI + vr);
                ldsm_x4_t(vl, sb + V_LO + vr);
                mma16816(o[2*p],   ph[s4], vh);
                mma16816(o[2*p],   ph[s4], vl);
                mma16816(o[2*p],   pl[s4], vh);
                mma16816(o[2*p+1], ph[s4], vh + 2);
                mma16816(o[2*p+1], ph[s4], vl + 2);
                mma16816(o[2*p+1], pl[s4], vh + 2);
            }
        }
        __syncthreads();   // before next iteration overwrites K/V
    }

    // ---- normalize + store ----
    float i0 = 1.f / l0, i1 = 1.f / l1;
    int r0 = q0 + w * 16 + g;
    #pragma unroll
    for (int f = 0; f < 16; f++) {
        float2 v0 = make_float2(o[f][0] * i0, o[f][1] * i0);
        float2 v1 = make_float2(o[f][2] * i1, o[f][3] * i1);
        *(float2*)(out + base + (size_t)r0 * H_ + f * 8 + tg * 2)       = v0;
        *(float2*)(out + base + (size_t)(r0 + 8) * H_ + f * 8 + tg * 2) = v1;
    }
}

// ---------------------------------------------------------------------------
extern "C" void kernel_launch(void* const* d_in, const int* in_sizes, int n_in,
                              void* d_out, int out_size)
{
    const float* input = (const float*)d_in[0];
    const float* Wq    = (const float*)d_in[1];
    const float* Wk    = (const float*)d_in[2];
    const float* Wv    = (const float*)d_in[3];
    float* out = (float*)d_out;

    cudaFuncSetAttribute(qkv_gemm, cudaFuncAttributeMaxDynamicSharedMemorySize, QKV_SMEM);
    cudaFuncSetAttribute(attn_mma, cudaFuncAttributeMaxDynamicSharedMemorySize, ATT_SMEM);

    convert_a_kernel<<<(M_TOT * D_ / 4) / 256, 256>>>(input);
    convert_w_kernel<<<dim3(512, 3), 256>>>(Wq, Wk, Wv);
    qkv_gemm<<<dim3(M_TOT / 128, 1, 3), 256, QKV_SMEM>>>();
    attn_mma<<<dim3(S_ / 64, B_), 128, ATT_SMEM>>>(out);
}